// round 16
// baseline (speedup 1.0000x reference)
#include <cuda_runtime.h>
#include <math.h>

// Problem constants
#define BB 512
#define TT 512
#define II 8
#define HH 256

// 16 batch tiles, each an 8-CTA cluster. 128 CTAs, 1/SM, single wave.
// h exchange: SMEM -> peer SMEM via cp.async.bulk (DSMEM engine) + mbarrier.
#define NBT 16
#define NCT 8
#define BT 32          // batch rows per tile
#define CT 32          // h cols per CTA (=> 96 gh rows r,z,n)
#define NCTAS (NBT * NCT)
#define NTHREADS 256   // 8 warps = 4 rowGroups x 2 colGroups

#define WS_PITCH 65    // float4 per W_hh row (2-phase-min banks)
#define WIH_PITCH 10

// SMEM layout (bytes); identical in all CTAs (DSMEM addressing)
#define OFF_WS   0
#define SZ_WS    (96 * WS_PITCH * 16)            // 99840
#define OFF_HB0  SZ_WS                           // h buf 0: 8 slices x 4096
#define SZ_HB    (8 * 4096)                      // 32768
#define OFF_HB1  (OFF_HB0 + SZ_HB)               // 132608
#define OFF_STG  (OFF_HB1 + SZ_HB)               // 165376: 2 x 4096 staging
#define OFF_WLIN (OFF_STG + 8192)                // 173568: 256 f32
#define OFF_WIH  (OFF_WLIN + 1024)               // 174592: 96*WIH_PITCH f32
#define OFF_XS   (OFF_WIH + 96 * WIH_PITCH * 4)  // 178432: 32*8 f32
#define OFF_BIH  (OFF_XS + BT * 8 * 4)           // 179456: 96 f32
#define OFF_BHH  (OFF_BIH + 96 * 4)              // 179840: 96 f32
#define OFF_MBAR (OFF_BHH + 96 * 4)              // 180224: 4 x 8B mbarriers
#define SMEM_TOTAL (OFF_MBAR + 32)               // 180256

__device__ __forceinline__ unsigned smem_u32(const void* p) {
    unsigned a;
    asm("{ .reg .u64 t; cvta.to.shared.u64 t, %1; cvt.u32.u64 %0, t; }"
        : "=r"(a) : "l"(p));
    return a;
}

__device__ __forceinline__ unsigned mapa_u32(unsigned addr, unsigned rank) {
    unsigned r;
    asm("mapa.shared::cluster.u32 %0, %1, %2;" : "=r"(r) : "r"(addr), "r"(rank));
    return r;
}

__device__ __forceinline__ void mbar_init(unsigned addr, unsigned cnt) {
    asm volatile("mbarrier.init.shared.b64 [%0], %1;" :: "r"(addr), "r"(cnt) : "memory");
}

__device__ __forceinline__ void mbar_expect_tx(unsigned addr, unsigned bytes) {
    asm volatile("mbarrier.arrive.expect_tx.shared.b64 _, [%0], %1;"
                 :: "r"(addr), "r"(bytes) : "memory");
}

__device__ __forceinline__ void mbar_wait(unsigned addr, unsigned parity) {
    unsigned done;
    asm volatile(
        "{\n\t.reg .pred p;\n\t"
        "mbarrier.try_wait.parity.acquire.cta.shared::cta.b64 p, [%1], %2;\n\t"
        "selp.b32 %0, 1, 0, p;\n\t}"
        : "=r"(done) : "r"(addr), "r"(parity) : "memory");
    if (!done) {
        asm volatile(
            "{\n\t.reg .pred P1;\n\t"
            "WL_%=:\n\t"
            "mbarrier.try_wait.parity.acquire.cta.shared::cta.b64 P1, [%0], %1, 0x989680;\n\t"
            "@P1 bra.uni WD_%=;\n\t"
            "bra.uni WL_%=;\n\t"
            "WD_%=:\n\t}"
            :: "r"(addr), "r"(parity) : "memory");
    }
}

// SMEM -> peer-SMEM bulk copy; complete_tx lands on (mapa'd) mbar.
__device__ __forceinline__ void bulk_dsmem(unsigned dst, unsigned src,
                                           unsigned bytes, unsigned mbar) {
    asm volatile(
        "cp.async.bulk.shared::cluster.shared::cta.mbarrier::complete_tx::bytes "
        "[%0], [%1], %2, [%3];"
        :: "r"(dst), "r"(src), "r"(bytes), "r"(mbar) : "memory");
}

#define CLUSTER_SYNC()                                                  \
  do {                                                                  \
    asm volatile("barrier.cluster.arrive.aligned;" ::: "memory");       \
    asm volatile("barrier.cluster.wait.aligned;"   ::: "memory");       \
  } while (0)

__device__ __forceinline__ float sigmoidf_fast(float v) {
    return 1.0f / (1.0f + __expf(-v));
}

__device__ __forceinline__ float tanh_fast(float v) {
    v = fminf(fmaxf(v, -15.0f), 15.0f);
    float e = __expf(-2.0f * v);
    return __fdividef(1.0f - e, 1.0f + e);
}

__device__ __forceinline__ void ffma2(unsigned long long& d,
                                      unsigned long long a,
                                      unsigned long long b) {
    asm("fma.rn.f32x2 %0, %1, %2, %0;" : "+l"(d) : "l"(a), "l"(b));
}

__device__ __forceinline__ float f2sum(unsigned long long v) {
    return __uint_as_float((unsigned)v) + __uint_as_float((unsigned)(v >> 32));
}

// GEMM over one half (4 slices) of the slice-major h tile.
#define GEMM_HALF(HB, H)                                                      \
  _Pragma("unroll")                                                           \
  for (int s = (H) * 4; s < (H) * 4 + 4; s++) {                               \
    const char* hsl = (HB) + s * 4096 + r0 * 128;                             \
    _Pragma("unroll")                                                         \
    for (int kk = 0; kk < 8; kk++) {                                          \
      const int k4 = s * 8 + kk;                                              \
      ulonglong2 w0 = w0q[k4], w1 = w1q[k4], w2 = w2q[k4];                    \
      _Pragma("unroll")                                                       \
      for (int i = 0; i < 4; i++) {                                           \
        ulonglong2 hv = *(const ulonglong2*)(hsl + i * 128 + kk * 16);        \
        ffma2(acc0[i], hv.x, w0.x); ffma2(acc0[i], hv.y, w0.y);               \
        ffma2(acc1[i], hv.x, w1.x); ffma2(acc1[i], hv.y, w1.y);               \
        ffma2(acc2[i], hv.x, w2.x); ffma2(acc2[i], hv.y, w2.y);               \
      }                                                                       \
    }                                                                         \
  }

// Per-warp pred over OWN 8 rows (colGroup 0 warps of the pred CTA).
// lane: prow = rowGroup*8 + (lane>>2); q = lane&3 covers slices {2q, 2q+1}.
#define PRED_OWN_ROWS(HBASE, TIDX)                                            \
  do {                                                                        \
    int prow_ = rowGroup * 8 + (lane >> 2);                                   \
    int q_ = lane & 3;                                                        \
    unsigned long long a_ = 0ull;                                             \
    _Pragma("unroll")                                                         \
    for (int ss = 0; ss < 2; ss++) {                                          \
      int sl = q_ * 2 + ss;                                                   \
      const ulonglong2* hr_ =                                                 \
          (const ulonglong2*)((HBASE) + sl * 4096 + prow_ * 128);             \
      const ulonglong2* wl_ = (const ulonglong2*)wlin + sl * 8;               \
      _Pragma("unroll")                                                       \
      for (int j = 0; j < 8; j++) {                                           \
        ulonglong2 hv = hr_[j], wv = wl_[j];                                  \
        ffma2(a_, hv.x, wv.x);                                                \
        ffma2(a_, hv.y, wv.y);                                                \
      }                                                                       \
    }                                                                         \
    float v_ = f2sum(a_);                                                     \
    v_ += __shfl_xor_sync(0xffffffffu, v_, 1);                                \
    v_ += __shfl_xor_sync(0xffffffffu, v_, 2);                                \
    if (q_ == 0)                                                              \
      out[(size_t)(b0 + prow_) * TT + (TIDX)] = v_ + blin;                    \
  } while (0)

__global__ void __launch_bounds__(NTHREADS, 1) __cluster_dims__(NCT, 1, 1)
gru_dsmem_bulk_kernel(const float* __restrict__ x,
                      const float* __restrict__ W_ih,
                      const float* __restrict__ W_hh,
                      const float* __restrict__ b_ih,
                      const float* __restrict__ b_hh,
                      const float* __restrict__ W_lin,
                      const float* __restrict__ b_lin,
                      float* __restrict__ out)
{
    extern __shared__ char sm[];
    float4* ws4  = (float4*)(sm + OFF_WS);       // [96][WS_PITCH]
    float*  wlin = (float*)(sm + OFF_WLIN);      // [256]
    float*  wih  = (float*)(sm + OFF_WIH);       // [96][WIH_PITCH]
    float*  xs   = (float*)(sm + OFF_XS);        // [32][8]
    float*  bihs = (float*)(sm + OFF_BIH);       // [96]
    float*  bhhs = (float*)(sm + OFF_BHH);       // [96]

    const int tid = threadIdx.x;
    const int cta = blockIdx.x;
    const int bt  = cta >> 3;                    // 0..15 (unused directly)
    const int ct  = cta & 7;                     // cluster rank
    const int b0  = (cta >> 3) * BT;
    const int j0  = ct * CT;
    const float blin = __ldg(&b_lin[0]);
    (void)bt;

    const unsigned hb0_u32 = smem_u32(sm + OFF_HB0);
    const unsigned hb1_u32 = smem_u32(sm + OFF_HB1);
    const unsigned stg_u32 = smem_u32(sm + OFF_STG);
    const unsigned mb_base = smem_u32(sm + OFF_MBAR);
    // mbar(buf,half) = mb_base + (buf*2+half)*8
    const unsigned mb00 = mb_base, mb01 = mb_base + 8;
    const unsigned mb10 = mb_base + 16, mb11 = mb_base + 24;

    // ---- one-time: weights into SMEM; zero h buffer 0 (h0 = 0) ----
    {
        const float4* whh4 = (const float4*)W_hh;
        for (int idx = tid; idx < 96 * 64; idx += NTHREADS) {
            int c = idx >> 6, k4 = idx & 63;
            int g = c >> 5, l = c & 31;
            int grow = g * HH + j0 + l;
            ws4[c * WS_PITCH + k4] = whh4[grow * (HH / 4) + k4];
        }
        for (int idx = tid; idx < 96 * WIH_PITCH; idx += NTHREADS) {
            int c = idx / WIH_PITCH, k = idx % WIH_PITCH;
            int g = c / 32, l = c % 32;
            int grow = g * HH + j0 + l;
            wih[idx] = (k < II) ? W_ih[grow * II + k] : 0.0f;
        }
        if (tid < 96) {
            int g = tid / 32, l = tid % 32;
            int grow = g * HH + j0 + l;
            bihs[tid] = b_ih[grow];
            bhhs[tid] = b_hh[grow];
        }
        for (int idx = tid; idx < 256; idx += NTHREADS) wlin[idx] = W_lin[idx];
        for (int idx = tid; idx < SZ_HB / 4; idx += NTHREADS)
            ((unsigned*)(sm + OFF_HB0))[idx] = 0u;
    }
    if (tid == 0) {
        mbar_init(mb00, 1); mbar_init(mb01, 1);
        mbar_init(mb10, 1); mbar_init(mb11, 1);
    }
    __syncthreads();
    CLUSTER_SYNC();   // mbarriers + SMEM live cluster-wide before any bulk

    // Warp decomposition: 8 warps = 4 rowGroups x 2 colGroups.
    const int wid = tid >> 5, lane = tid & 31;
    const int colGroup = wid & 1, rowGroup = wid >> 1;
    const int tx = lane & 15, ty = lane >> 4;
    const int localCol = colGroup * 16 + tx;     // 0..31
    const int r0 = rowGroup * 8 + ty * 4;        // this thread's 4 rows

    const ulonglong2* w0q = (const ulonglong2*)(ws4 + localCol * WS_PITCH);
    const ulonglong2* w1q = (const ulonglong2*)(ws4 + (32 + localCol) * WS_PITCH);
    const ulonglong2* w2q = (const ulonglong2*)(ws4 + (64 + localCol) * WS_PITCH);

    const unsigned long long* wxr = (const unsigned long long*)&wih[localCol * WIH_PITCH];
    const unsigned long long* wxz = (const unsigned long long*)&wih[(32 + localCol) * WIH_PITCH];
    const unsigned long long* wxn = (const unsigned long long*)&wih[(64 + localCol) * WIH_PITCH];
    const float bir = bihs[localCol], biz = bihs[32 + localCol], bin = bihs[64 + localCol];
    const float bhr = bhhs[localCol], bhz = bhhs[32 + localCol], bhn = bhhs[64 + localCol];

    float hreg[4] = {0.f, 0.f, 0.f, 0.f};
    int ph00 = 0, ph01 = 0, ph10 = 0, ph11 = 0;  // wait parities

    for (int t = 0; t < TT; t++) {
        const int p = t & 1, nb = p ^ 1;
        const char* hb = sm + (p ? OFF_HB1 : OFF_HB0);

        // arm receive barriers for the data produced THIS step (buffer nb).
        // Safe: peers can't publish nb-phase data before consuming our
        // p-phase slice (sent at end of this step); early arrivals are
        // handled by the signed tx-count anyway.
        if (tid == 0) {
            if (nb) { mbar_expect_tx(mb10, 16384); mbar_expect_tx(mb11, 16384); }
            else    { mbar_expect_tx(mb00, 16384); mbar_expect_tx(mb01, 16384); }
        }

        // x_t for this warp's rows (colGroup pair writes duplicate data)
        if (lane < 16) {
            int r = rowGroup * 8 + (lane >> 1), hf = lane & 1;
            const float4* xsrc = (const float4*)&x[((size_t)(b0 + r) * TT + t) * II];
            ((float4*)xs)[r * 2 + hf] = __ldg(&xsrc[hf]);
        }
        __syncwarp();

        unsigned long long acc0[4], acc1[4], acc2[4];
        #pragma unroll
        for (int i = 0; i < 4; i++) { acc0[i] = 0ull; acc1[i] = 0ull; acc2[i] = 0ull; }

        if (t > 0) {
            if (p) { mbar_wait(mb10, (unsigned)ph10); ph10 ^= 1; }
            else   { mbar_wait(mb00, (unsigned)ph00); ph00 ^= 1; }
            GEMM_HALF(hb, 0)
            if (p) { mbar_wait(mb11, (unsigned)ph11); ph11 ^= 1; }
            else   { mbar_wait(mb01, (unsigned)ph01); ph01 ^= 1; }
            GEMM_HALF(hb, 1)

            // pred[t-1] from the full local h_t tile (pred CTA only)
            if (ct == NCT - 1 && colGroup == 0) PRED_OWN_ROWS(hb, t - 1);
        }
        // t == 0: h_0 = 0 (hb0 zeroed) -> acc stays 0, no wait

        // ---- fused gates + h update; write slice into staging[nb] ----
        char* stg = sm + OFF_STG + nb * 4096;
        #pragma unroll
        for (int i = 0; i < 4; i++) {
            const int r = r0 + i;
            const unsigned long long* xq = (const unsigned long long*)&xs[r * II];
            unsigned long long ar = 0ull, az = 0ull, an = 0ull;
            #pragma unroll
            for (int kq = 0; kq < 4; kq++) {
                unsigned long long xv = xq[kq];
                ffma2(ar, xv, wxr[kq]);
                ffma2(az, xv, wxz[kq]);
                ffma2(an, xv, wxn[kq]);
            }
            float rr = sigmoidf_fast(bir + f2sum(ar) + f2sum(acc0[i]) + bhr);
            float zz = sigmoidf_fast(biz + f2sum(az) + f2sum(acc1[i]) + bhz);
            float nn = tanh_fast(bin + f2sum(an) + rr * (f2sum(acc2[i]) + bhn));
            float hn = (1.0f - zz) * nn + zz * hreg[i];
            hreg[i] = hn;
            *(float*)(stg + r * 128 + localCol * 4) = hn;
        }

        // ---- publish: one bulk per cluster CTA (incl. self), 4KB each ----
        __syncthreads();
        if (tid == 0) {
            asm volatile("fence.proxy.async.shared::cta;" ::: "memory");
            const unsigned src = stg_u32 + (unsigned)(nb * 4096);
            const unsigned dst_local = (nb ? hb1_u32 : hb0_u32) + (unsigned)(ct * 4096);
            const unsigned mb_local = mb_base + (unsigned)((nb * 2 + (ct >> 2)) * 8);
            #pragma unroll
            for (unsigned rk = 0; rk < NCT; rk++) {
                bulk_dsmem(mapa_u32(dst_local, rk), src, 4096u,
                           mapa_u32(mb_local, rk));
            }
        }
    }

    // ---- epilogue: absorb final inbound bulks (buffer 0), emit pred[TT-1] ----
    mbar_wait(mb00, (unsigned)ph00);
    mbar_wait(mb01, (unsigned)ph01);
    if (ct == NCT - 1 && colGroup == 0)
        PRED_OWN_ROWS(sm + OFF_HB0, TT - 1);
    __syncthreads();
    CLUSTER_SYNC();   // no CTA exits while peers' bulks may be in flight
}

extern "C" void kernel_launch(void* const* d_in, const int* in_sizes, int n_in,
                              void* d_out, int out_size) {
    const float* x     = (const float*)d_in[0];
    const float* W_ih  = (const float*)d_in[1];
    const float* W_hh  = (const float*)d_in[2];
    const float* b_ih  = (const float*)d_in[3];
    const float* b_hh  = (const float*)d_in[4];
    const float* W_lin = (const float*)d_in[5];
    const float* b_lin = (const float*)d_in[6];
    float* out = (float*)d_out;

    cudaFuncSetAttribute(gru_dsmem_bulk_kernel,
                         cudaFuncAttributeMaxDynamicSharedMemorySize, SMEM_TOTAL);

    gru_dsmem_bulk_kernel<<<NCTAS, NTHREADS, SMEM_TOTAL>>>(
        x, W_ih, W_hh, b_ih, b_hh, W_lin, b_lin, out);
}

// round 17
// speedup vs baseline: 1.2954x; 1.2954x over previous
#include <cuda_runtime.h>
#include <math.h>

// Problem constants
#define BB 512
#define TT 512
#define II 8
#define HH 256

// 16 batch tiles x 8 col-CTAs = 128 CTAs, 1/SM, single wave.
// KEY CHANGE vs R15: W_hh lives in REGISTERS (persistent), not SMEM ->
// crossbar traffic drops ~4x (no W re-streaming, no rowGroup duplication).
#define NBT 16
#define NCT 8
#define BT 32          // batch rows per tile
#define CT 32          // h cols per CTA (=> 96 gh rows r,z,n)
#define NCTAS (NBT * NCT)
#define NTHREADS 256   // 8 warps; warp = 4 cols x 8 ksegs
#define WIH_PITCH 10

// SMEM (static): h tile 32KB (swizzled) + small tables
#define OFF_HS   0
#define SZ_HS    (BT * 1024)                   // 32768; row pitch 1024B
#define OFF_WIH  SZ_HS                         // 96 x WIH_PITCH f32 = 3840
#define OFF_XS   (OFF_WIH + 96 * WIH_PITCH * 4)// 32 x 8 f32 = 1024
#define OFF_BIH  (OFF_XS + 1024)               // 96 f32
#define OFF_BHH  (OFF_BIH + 384)               // 96 f32
#define OFF_WLIN (OFF_BHH + 384)               // 256 f32 (PERMUTED, see swz)
#define SM_BYTES (OFF_WLIN + 1024)             // 39424

// h tile swizzle: 16B unit u (k = 4u; u = s*8 + kk) stored at pos = kk*8 + s.
// => lanes s=0..7 reading (row, kk) hit 128B contiguous -> conflict-free.
#define SWZ(u) ((((u) & 7) << 3) | ((u) >> 3))

// Persistent device state
__device__ float g_h[2][BB][HH];
__device__ unsigned g_flag[NBT][NCT][32];
__device__ unsigned g_bar_count = 0;
__device__ unsigned g_bar_gen = 0;

__device__ __forceinline__ void grid_barrier() {   // end-of-kernel only
    __syncthreads();
    if (threadIdx.x == 0) {
        __threadfence();
        volatile unsigned* vgen = (volatile unsigned*)&g_bar_gen;
        unsigned gen = *vgen;
        unsigned arrived = atomicAdd(&g_bar_count, 1u);
        if (arrived == NCTAS - 1u) {
            *((volatile unsigned*)&g_bar_count) = 0u;
            __threadfence();
            *vgen = gen + 1u;
        } else {
            while (*vgen == gen) { }
        }
        __threadfence();
    }
    __syncthreads();
}

__device__ __forceinline__ unsigned ld_acq_gpu(const unsigned* p) {
    unsigned v;
    asm volatile("ld.acquire.gpu.u32 %0, [%1];" : "=r"(v) : "l"(p) : "memory");
    return v;
}

__device__ __forceinline__ void st_rel_gpu(unsigned* p, unsigned v) {
    asm volatile("st.release.gpu.u32 [%0], %1;" :: "l"(p), "r"(v) : "memory");
}

__device__ __forceinline__ float sigmoidf_fast(float v) {
    return 1.0f / (1.0f + __expf(-v));
}

__device__ __forceinline__ float tanh_fast(float v) {
    v = fminf(fmaxf(v, -15.0f), 15.0f);
    float e = __expf(-2.0f * v);
    return __fdividef(1.0f - e, 1.0f + e);
}

__device__ __forceinline__ void ffma2(unsigned long long& d,
                                      unsigned long long a,
                                      unsigned long long b) {
    asm("fma.rn.f32x2 %0, %1, %2, %0;" : "+l"(d) : "l"(a), "l"(b));
}

__device__ __forceinline__ float f2sum(unsigned long long v) {
    return __uint_as_float((unsigned)v) + __uint_as_float((unsigned)(v >> 32));
}

__device__ __forceinline__ void cp16(unsigned dst, const void* src) {
    asm volatile("cp.async.cg.shared.global [%0], [%1], 16;"
                 :: "r"(dst), "l"(src) : "memory");
}

__device__ __forceinline__ unsigned long long pack2(float a, float b) {
    return (unsigned long long)__float_as_uint(a)
         | ((unsigned long long)__float_as_uint(b) << 32);
}

__global__ void __launch_bounds__(NTHREADS, 1)
gru_wreg_kernel(const float* __restrict__ x,
                const float* __restrict__ W_ih,
                const float* __restrict__ W_hh,
                const float* __restrict__ b_ih,
                const float* __restrict__ b_hh,
                const float* __restrict__ W_lin,
                const float* __restrict__ b_lin,
                float* __restrict__ out)
{
    __shared__ __align__(16) char sm[SM_BYTES];
    char*  hs   = sm + OFF_HS;
    float* wih  = (float*)(sm + OFF_WIH);
    float* xs   = (float*)(sm + OFF_XS);
    float* bihs = (float*)(sm + OFF_BIH);
    float* bhhs = (float*)(sm + OFF_BHH);
    float* wlns = (float*)(sm + OFF_WLIN);

    const int tid = threadIdx.x;
    const int cta = blockIdx.x;
    const int bt  = cta >> 3;
    const int ct  = cta & 7;
    const int b0  = bt * BT;
    const int j0  = ct * CT;
    const float blin = __ldg(&b_lin[0]);

    const int wid = tid >> 5, lane = tid & 31;
    const int cl  = lane >> 3;                   // 0..3 col within warp group
    const int s   = lane & 7;                    // 0..7 kseg (32 k each)
    const int lc  = wid * 4 + cl;                // 0..31 local h col
    const int mycol = j0 + lc;                   // global h col this thread outputs
    const unsigned hs_u32 = (unsigned)__cvta_generic_to_shared(hs);

    // ---- one-time: W_hh slice -> REGISTERS (3 gates x 32 k = 48 u64) ----
    unsigned long long wreg[3][16];
    #pragma unroll
    for (int g = 0; g < 3; g++) {
        const float* wrow = &W_hh[((size_t)g * HH + mycol) * HH + s * 32];
        #pragma unroll
        for (int u = 0; u < 16; u++)
            wreg[g][u] = pack2(wrow[2 * u], wrow[2 * u + 1]);
    }

    // ---- one-time: small tables into SMEM ----
    for (int idx = tid; idx < 96 * WIH_PITCH; idx += NTHREADS) {
        int c = idx / WIH_PITCH, k = idx % WIH_PITCH;
        int g = c / 32, l = c % 32;
        wih[idx] = (k < II) ? W_ih[(g * HH + j0 + l) * II + k] : 0.0f;
    }
    if (tid < 96) {
        int g = tid / 32, l = tid % 32;
        bihs[tid] = b_ih[g * HH + j0 + l];
        bhhs[tid] = b_hh[g * HH + j0 + l];
    }
    if (tid < 256) {
        int pos = tid >> 2, w = tid & 3;
        int u = SWZ(pos);                        // involution: orig unit at pos
        wlns[tid] = W_lin[u * 4 + w];
    }
    __syncthreads();

    const unsigned long long* wxr = (const unsigned long long*)&wih[lc * WIH_PITCH];
    const unsigned long long* wxz = (const unsigned long long*)&wih[(32 + lc) * WIH_PITCH];
    const unsigned long long* wxn = (const unsigned long long*)&wih[(64 + lc) * WIH_PITCH];

    for (int t = 0; t < TT; t++) {
        const int p = t & 1, nb = p ^ 1;

        if (t > 0) {
            if (tid < NCT) {
                const unsigned* f = &g_flag[bt][tid][0];
                while (ld_acq_gpu(f) < (unsigned)t) { }
            }
            __syncthreads();
            // fetch full h_t tile (32KB) into swizzled SMEM
            #pragma unroll
            for (int it = 0; it < 8; it++) {
                int idx = it * NTHREADS + tid;   // 0..2047
                int row = idx >> 6, u = idx & 63;
                cp16(hs_u32 + (unsigned)(row * 1024 + SWZ(u) * 16),
                     (const float4*)&g_h[p][b0 + row][0] + u);
            }
            asm volatile("cp.async.commit_group;" ::: "memory");
        }

        // x_t tile [32][8]
        if (tid < BT * 2) {
            int r = tid >> 1, hf = tid & 1;
            const float4* xsrc = (const float4*)&x[((size_t)(b0 + r) * TT + t) * II];
            ((float4*)xs)[r * 2 + hf] = __ldg(&xsrc[hf]);
        }

        if (t > 0) asm volatile("cp.async.wait_group 0;" ::: "memory");
        __syncthreads();

        // ---- pred[t-1] on pred CTA (tile = h_t is ready) ----
        if (ct == NCT - 1 && t > 0) {
            int prow = wid * 4 + (lane >> 3);
            int q = lane & 7;
            unsigned long long a = 0ull;
            const char* hr = hs + prow * 1024;
            #pragma unroll
            for (int j = 0; j < 8; j++) {
                int pos = q * 8 + j;
                ulonglong2 hv = *(const ulonglong2*)(hr + pos * 16);
                ulonglong2 wv = ((const ulonglong2*)wlns)[pos];
                ffma2(a, hv.x, wv.x);
                ffma2(a, hv.y, wv.y);
            }
            float v = f2sum(a);
            v += __shfl_xor_sync(0xffffffffu, v, 1);
            v += __shfl_xor_sync(0xffffffffu, v, 2);
            v += __shfl_xor_sync(0xffffffffu, v, 4);
            if (q == 0)
                out[(size_t)(b0 + prow) * TT + (t - 1)] = v + blin;
        }

        // ---- 8 batches of 4 rows: GEMM (k-split) + reduce + gates ----
        #pragma unroll 1
        for (int rb = 0; rb < 8; rb++) {
            unsigned long long acc[3][4];
            #pragma unroll
            for (int g = 0; g < 3; g++)
                #pragma unroll
                for (int i = 0; i < 4; i++) acc[g][i] = 0ull;

            if (t > 0) {
                const char* hrb = hs + (rb * 4) * 1024 + s * 16;
                #pragma unroll
                for (int kk = 0; kk < 8; kk++) {
                    #pragma unroll
                    for (int i = 0; i < 4; i++) {
                        ulonglong2 hv = *(const ulonglong2*)
                            (hrb + i * 1024 + kk * 128);
                        ffma2(acc[0][i], hv.x, wreg[0][2 * kk]);
                        ffma2(acc[0][i], hv.y, wreg[0][2 * kk + 1]);
                        ffma2(acc[1][i], hv.x, wreg[1][2 * kk]);
                        ffma2(acc[1][i], hv.y, wreg[1][2 * kk + 1]);
                        ffma2(acc[2][i], hv.x, wreg[2][2 * kk]);
                        ffma2(acc[2][i], hv.y, wreg[2][2 * kk + 1]);
                    }
                }
            }

            // reduce over ksegs (lane low-3 bits); lane s==i keeps row i's sum
            float sr = 0.f, sz = 0.f, sn = 0.f;
            #pragma unroll
            for (int i = 0; i < 4; i++) {
                float v0 = f2sum(acc[0][i]);
                v0 += __shfl_xor_sync(0xffffffffu, v0, 1);
                v0 += __shfl_xor_sync(0xffffffffu, v0, 2);
                v0 += __shfl_xor_sync(0xffffffffu, v0, 4);
                float v1 = f2sum(acc[1][i]);
                v1 += __shfl_xor_sync(0xffffffffu, v1, 1);
                v1 += __shfl_xor_sync(0xffffffffu, v1, 2);
                v1 += __shfl_xor_sync(0xffffffffu, v1, 4);
                float v2 = f2sum(acc[2][i]);
                v2 += __shfl_xor_sync(0xffffffffu, v2, 1);
                v2 += __shfl_xor_sync(0xffffffffu, v2, 2);
                v2 += __shfl_xor_sync(0xffffffffu, v2, 4);
                if (s == i) { sr = v0; sz = v1; sn = v2; }
            }

            // gates on lanes s<4 (row = rb*4 + s, col = mycol)
            if (s < 4) {
                const int row = rb * 4 + s;
                const unsigned long long* xq =
                    (const unsigned long long*)&xs[row * II];
                unsigned long long ar = 0ull, az = 0ull, an = 0ull;
                #pragma unroll
                for (int kq = 0; kq < 4; kq++) {
                    unsigned long long xv = xq[kq];
                    ffma2(ar, xv, wxr[kq]);
                    ffma2(az, xv, wxz[kq]);
                    ffma2(an, xv, wxn[kq]);
                }
                float hold = 0.0f;
                if (t > 0) {
                    int u = mycol >> 2;
                    hold = *(const float*)(hs + row * 1024 + SWZ(u) * 16
                                           + (mycol & 3) * 4);
                }
                float rr = sigmoidf_fast(bihs[lc] + f2sum(ar) + sr + bhhs[lc]);
                float zz = sigmoidf_fast(bihs[32 + lc] + f2sum(az) + sz + bhhs[32 + lc]);
                float nn = tanh_fast(bihs[64 + lc] + f2sum(an)
                                     + rr * (sn + bhhs[64 + lc]));
                float hn = (1.0f - zz) * nn + zz * hold;
                __stcg(&g_h[nb][b0 + row][mycol], hn);
            }
        }

        // ---- publish ----
        __syncthreads();
        if (tid == 0) st_rel_gpu(&g_flag[bt][ct][0], (unsigned)(t + 1));
    }

    // ---- epilogue: pred[TT-1] on pred CTA from h_TT (buf 0) ----
    if (ct == NCT - 1) {
        if (tid < NCT) {
            const unsigned* f = &g_flag[bt][tid][0];
            while (ld_acq_gpu(f) < (unsigned)TT) { }
        }
        __syncthreads();
        #pragma unroll
        for (int it = 0; it < 8; it++) {
            int idx = it * NTHREADS + tid;
            int row = idx >> 6, u = idx & 63;
            cp16(hs_u32 + (unsigned)(row * 1024 + SWZ(u) * 16),
                 (const float4*)&g_h[0][b0 + row][0] + u);
        }
        asm volatile("cp.async.commit_group;" ::: "memory");
        asm volatile("cp.async.wait_group 0;" ::: "memory");
        __syncthreads();
        {
            int prow = wid * 4 + (lane >> 3);
            int q = lane & 7;
            unsigned long long a = 0ull;
            const char* hr = hs + prow * 1024;
            #pragma unroll
            for (int j = 0; j < 8; j++) {
                int pos = q * 8 + j;
                ulonglong2 hv = *(const ulonglong2*)(hr + pos * 16);
                ulonglong2 wv = ((const ulonglong2*)wlns)[pos];
                ffma2(a, hv.x, wv.x);
                ffma2(a, hv.y, wv.y);
            }
            float v = f2sum(a);
            v += __shfl_xor_sync(0xffffffffu, v, 1);
            v += __shfl_xor_sync(0xffffffffu, v, 2);
            v += __shfl_xor_sync(0xffffffffu, v, 4);
            if (q == 0)
                out[(size_t)(b0 + prow) * TT + (TT - 1)] = v + blin;
        }
    }

    // ---- all done; reset own flag for next graph replay ----
    grid_barrier();
    if (tid == 0) g_flag[bt][ct][0] = 0u;
}

extern "C" void kernel_launch(void* const* d_in, const int* in_sizes, int n_in,
                              void* d_out, int out_size) {
    const float* x     = (const float*)d_in[0];
    const float* W_ih  = (const float*)d_in[1];
    const float* W_hh  = (const float*)d_in[2];
    const float* b_ih  = (const float*)d_in[3];
    const float* b_hh  = (const float*)d_in[4];
    const float* W_lin = (const float*)d_in[5];
    const float* b_lin = (const float*)d_in[6];
    float* out = (float*)d_out;

    gru_wreg_kernel<<<NCTAS, NTHREADS>>>(
        x, W_ih, W_hh, b_ih, b_hh, W_lin, b_lin, out);
}